// round 7
// baseline (speedup 1.0000x reference)
#include <cuda_runtime.h>
#include <math.h>
#include <stdint.h>

#define B_ 2
#define C_ 96
#define D_ 8
#define H_ 48
#define W_ 48
#define L_ (D_*H_*W_)          // 18432
#define NROWS (B_*L_)          // 36864
#define DSTATE 16
#define DINNER 192
#define NC 72
#define CS (L_/NC)             // 256

// ---------------- scratch ----------------
__device__ float g_h1[B_*C_*L_];
__device__ float g_h2[B_*4*C_*L_];
__device__ float g_xflat[NROWS*C_];
__device__ float g_xn[NROWS*C_];
__device__ float g_xzT[2*DINNER*NROWS];
__device__ float g_uT[DINNER*NROWS];
__device__ float g_xdT[38*NROWS];
__device__ float g_dtT[DINNER*NROWS];
__device__ float g_yT[DINNER*NROWS];
__device__ float g_outm[NROWS*C_];
__device__ float g_xm2[NROWS*C_];
__device__ float g_stats[32];
__device__ float g_gnsc[B_*C_];
__device__ float g_gnsh[B_*C_];
__device__ float g_P[NC*384*DSTATE];
__device__ float g_F[NC*384*DSTATE];
__device__ float g_Hi[NC*384*DSTATE];

__device__ __forceinline__ float siluf(float x) { return x / (1.f + __expf(-x)); }
__device__ __forceinline__ float geluf(float x) {
    return 0.5f * x * (1.f + erff(x * 0.70710678118654752f));
}
__device__ __forceinline__ unsigned f2tf(float x) {
    unsigned r;
    asm("cvt.rna.tf32.f32 %0, %1;" : "=r"(r) : "f"(x));
    return r;
}
__device__ __forceinline__ void mma_tf32(float c[4], const unsigned a[4], const unsigned b[2]) {
    asm("mma.sync.aligned.m16n8k8.row.col.f32.tf32.tf32.f32 "
        "{%0,%1,%2,%3}, {%4,%5,%6,%7}, {%8,%9}, {%0,%1,%2,%3};"
        : "+f"(c[0]), "+f"(c[1]), "+f"(c[2]), "+f"(c[3])
        : "r"(a[0]), "r"(a[1]), "r"(a[2]), "r"(a[3]), "r"(b[0]), "r"(b[1]));
}

// ---------------- depthwise conv3d + bias + fused GN stats ----------------
__global__ __launch_bounds__(256) void dwconv3d_kernel(const float* __restrict__ x,
                                                       const float* __restrict__ w,
                                                       const float* __restrict__ bias) {
    __shared__ float s[10][22][22];
    __shared__ float wsm[147];
    __shared__ float r1[8], r2[8];
    int bc = blockIdx.z;
    int c = bc % C_;
    int b = bc / C_;
    int h0 = blockIdx.y * 16, w0 = blockIdx.x * 16;
    int tid = threadIdx.y * 16 + threadIdx.x;
    const float* xp = x + (size_t)bc * L_;
    for (int i = tid; i < 147; i += 256) wsm[i] = w[c*147 + i];
    for (int i = tid; i < 10*22*22; i += 256) {
        int dd = i / 484; int r = i % 484; int hh = r / 22; int ww = r % 22;
        int d = dd - 1, h = h0 + hh - 3, wq = w0 + ww - 3;
        float v = 0.f;
        if (d >= 0 && d < D_ && h >= 0 && h < H_ && wq >= 0 && wq < W_)
            v = xp[(d*H_ + h)*W_ + wq];
        s[dd][hh][ww] = v;
    }
    __syncthreads();
    int ty = threadIdx.y, tx = threadIdx.x;
    float bv = bias[c];
    float acc[8];
    #pragma unroll
    for (int i = 0; i < 8; i++) acc[i] = bv;
    #pragma unroll
    for (int dd = 0; dd < 10; dd++) {
        #pragma unroll
        for (int kh = 0; kh < 7; kh++) {
            #pragma unroll
            for (int kw = 0; kw < 7; kw++) {
                float v = s[dd][ty+kh][tx+kw];
                #pragma unroll
                for (int kd = 0; kd < 3; kd++) {
                    int od = dd - kd;
                    if (od >= 0 && od < 8)
                        acc[od] += v * wsm[kd*49 + kh*7 + kw];
                }
            }
        }
    }
    size_t base = (size_t)bc * L_;
    float s1 = 0.f, s2 = 0.f;
    #pragma unroll
    for (int od = 0; od < 8; od++) {
        g_h1[base + (od*H_ + h0 + ty)*W_ + (w0 + tx)] = acc[od];
        s1 += acc[od]; s2 += acc[od]*acc[od];
    }
    #pragma unroll
    for (int k = 16; k > 0; k >>= 1) {
        s1 += __shfl_xor_sync(0xffffffffu, s1, k);
        s2 += __shfl_xor_sync(0xffffffffu, s2, k);
    }
    if ((tid & 31) == 0) { r1[tid >> 5] = s1; r2[tid >> 5] = s2; }
    __syncthreads();
    if (tid == 0) {
        float t1 = 0.f, t2 = 0.f;
        #pragma unroll
        for (int i = 0; i < 8; i++) { t1 += r1[i]; t2 += r2[i]; }
        int z = b*8 + c/12;
        atomicAdd(&g_stats[z*2], t1);
        atomicAdd(&g_stats[z*2+1], t2);
    }
}

__global__ void zero_stats_kernel() { if (threadIdx.x < 32) g_stats[threadIdx.x] = 0.f; }

__global__ void gn_scale_kernel(const float* __restrict__ gg, const float* __restrict__ gb) {
    int i = threadIdx.x;
    if (i >= B_*C_) return;
    int b = i / C_, c = i % C_;
    int z = b*8 + c/12;
    float cnt = 12.f * (float)L_;
    float mu = g_stats[z*2] / cnt;
    float var = g_stats[z*2+1] / cnt - mu*mu;
    float inv = rsqrtf(var + 1e-5f);
    g_gnsc[i] = inv * gg[c];
    g_gnsh[i] = gb[c] - mu * inv * gg[c];
}

// ---------------- GEMM v5: tf32 mma, permuted smem (LDS.128/LDS.64 fragments) --------
// A layout: As3[rr][g*32 + r*4 + half*2 + hi], rr=ks*4+cq  (k=ks*8+half*4+cq, m=g*16+hi*8+r)
// W layout: Ws3[rr][n*2 + half]
template<bool A_KM, bool OUT_NM, int ACT, bool ACC, bool NORM>
__global__ __launch_bounds__(256, 2) void gemmt_kernel(
    const float* __restrict__ A, const float* __restrict__ Wt,
    const float* __restrict__ bias, float* __restrict__ Co,
    int M, int N, int K, size_t aBatch, size_t cBatch,
    const float* __restrict__ nscB, const float* __restrict__ nshB)
{
    __shared__ unsigned As3[8][264];
    __shared__ unsigned Ws3[8][264];
    int m0 = blockIdx.x * 128, n0 = blockIdx.y * 128;
    A  += (size_t)blockIdx.z * aBatch;
    Co += (size_t)blockIdx.z * cBatch;
    const float* nsc = NORM ? (nscB + blockIdx.z * C_) : nullptr;
    const float* nsh = NORM ? (nshB + blockIdx.z * C_) : nullptr;
    int tid = threadIdx.x;
    int lane = tid & 31;
    int warp = tid >> 5;
    int wm = (warp & 1) * 64;
    int wn = (warp >> 1) * 32;
    int r = lane >> 2, cq = lane & 3;

    float cacc[4][4][4];
    #pragma unroll
    for (int mt = 0; mt < 4; mt++)
        #pragma unroll
        for (int nt = 0; nt < 4; nt++)
            #pragma unroll
            for (int e = 0; e < 4; e++) cacc[mt][nt][e] = 0.f;

    for (int k0 = 0; k0 < K; k0 += 16) {
        // ---- stage A tile ----
        if (A_KM) {
            #pragma unroll
            for (int t = 0; t < 2; t++) {
                int f = tid + t*256;
                int kk = f >> 5; int p4 = (f & 31) << 2;
                float4 v = *(const float4*)(A + (size_t)(k0+kk)*M + m0 + p4);
                if (NORM) {
                    float sc = __ldg(&nsc[k0+kk]), sh = __ldg(&nsh[k0+kk]);
                    v.x = v.x*sc + sh; v.y = v.y*sc + sh;
                    v.z = v.z*sc + sh; v.w = v.w*sc + sh;
                }
                int rr = ((kk >> 3) << 2) | (kk & 3);
                int half = (kk >> 2) & 1;
                #pragma unroll
                for (int j = 0; j < 4; j++) {
                    int m = p4 + j;
                    int p = ((m >> 4) << 5) + ((m & 7) << 2) + half*2 + ((m >> 3) & 1);
                    As3[rr][p] = f2tf((&v.x)[j]);
                }
            }
        } else {
            #pragma unroll
            for (int t = 0; t < 2; t++) {
                int f = tid + t*256;
                int mm = f >> 2; int q4 = (f & 3) << 2;
                float4 v = *(const float4*)(A + (size_t)(m0+mm)*K + k0 + q4);
                int pbase = ((mm >> 4) << 5) + ((mm & 7) << 2) + ((mm >> 3) & 1);
                #pragma unroll
                for (int j = 0; j < 4; j++) {
                    int kk = q4 + j;
                    int rr = ((kk >> 3) << 2) | (kk & 3);
                    int half = (kk >> 2) & 1;
                    As3[rr][pbase + half*2] = f2tf((&v.x)[j]);
                }
            }
        }
        // ---- stage W tile ----
        #pragma unroll
        for (int t = 0; t < 2; t++) {
            int f = tid + t*256;
            int nn = f >> 2; int q4 = (f & 3) << 2;
            float4 v = make_float4(0.f, 0.f, 0.f, 0.f);
            if (n0 + nn < N) v = *(const float4*)(Wt + (size_t)(n0+nn)*K + k0 + q4);
            #pragma unroll
            for (int j = 0; j < 4; j++) {
                int kk = q4 + j;
                int rr = ((kk >> 3) << 2) | (kk & 3);
                int half = (kk >> 2) & 1;
                Ws3[rr][nn*2 + half] = f2tf((&v.x)[j]);
            }
        }
        __syncthreads();
        #pragma unroll
        for (int ks = 0; ks < 2; ks++) {
            int rr = ks*4 + cq;
            unsigned af[4][4];
            #pragma unroll
            for (int mt = 0; mt < 4; mt++) {
                uint4 a4 = *(const uint4*)&As3[rr][((wm >> 4) + mt)*32 + r*4];
                af[mt][0] = a4.x; af[mt][1] = a4.y; af[mt][2] = a4.z; af[mt][3] = a4.w;
            }
            unsigned bf[4][2];
            #pragma unroll
            for (int nt = 0; nt < 4; nt++) {
                uint2 b2 = *(const uint2*)&Ws3[rr][(wn + nt*8 + r)*2];
                bf[nt][0] = b2.x; bf[nt][1] = b2.y;
            }
            #pragma unroll
            for (int mt = 0; mt < 4; mt++)
                #pragma unroll
                for (int nt = 0; nt < 4; nt++)
                    mma_tf32(cacc[mt][nt], af[mt], bf[nt]);
        }
        __syncthreads();
    }

    // ---- epilogue ----
    int er = lane >> 2, j2 = (lane & 3) * 2;
    #pragma unroll
    for (int mt = 0; mt < 4; mt++)
        #pragma unroll
        for (int nt = 0; nt < 4; nt++) {
            int mb = m0 + wm + mt*16 + er;
            int nb = n0 + wn + nt*8 + j2;
            #pragma unroll
            for (int e = 0; e < 4; e++) {
                int m = mb + ((e >> 1) ? 8 : 0);
                int n = nb + (e & 1);
                if (n < N) {
                    float v = cacc[mt][nt][e] + (bias ? bias[n] : 0.f);
                    if (ACT == 1) v = geluf(v);
                    size_t off = OUT_NM ? ((size_t)n*M + m) : ((size_t)m*N + n);
                    if (ACC) v += Co[off];
                    Co[off] = v;
                }
            }
        }
}

// ---------------- LayerNorm over C with transpose ----------------
__global__ __launch_bounds__(256) void ln1_kernel(const float* __restrict__ x,
                                                  const float* __restrict__ g,
                                                  const float* __restrict__ bta) {
    __shared__ float s[96][33];
    __shared__ float mu_s[32], rs_s[32];
    int b = blockIdx.y;
    int l0 = blockIdx.x * 32;
    int tid = threadIdx.x;
    int tx = tid & 31, ty = tid >> 5;
    const float* xp = x + (size_t)b * C_ * L_;
    for (int c = ty; c < C_; c += 8)
        s[c][tx] = xp[(size_t)c * L_ + l0 + tx];
    __syncthreads();
    if (tid < 32) {
        float sum = 0.f, sq = 0.f;
        #pragma unroll 4
        for (int c = 0; c < C_; c++) { float v = s[c][tid]; sum += v; sq += v*v; }
        float mu = sum / 96.f;
        float var = sq / 96.f - mu*mu;
        mu_s[tid] = mu; rs_s[tid] = rsqrtf(var + 1e-5f);
    }
    __syncthreads();
    for (int idx = tid; idx < 96*32; idx += 256) {
        int c = idx % 96, l = idx / 96;
        float v = s[c][l];
        size_t row = (size_t)(b*L_ + l0 + l);
        g_xflat[row*96 + c] = v;
        g_xn[row*96 + c] = (v - mu_s[l]) * rs_s[l] * g[c] + bta[c];
    }
}

// ---------------- causal depthwise conv1d (k=4) + SiLU ----------------
__global__ __launch_bounds__(256) void conv1d_kernel(const float* __restrict__ w,
                                                     const float* __restrict__ bias) {
    int idx = blockIdx.x * 256 + threadIdx.x;
    int lb = idx % (L_/4);
    int db = idx / (L_/4);
    if (db >= DINNER * B_) return;
    int b = db % B_, d = db / B_;
    const float* xp = g_xzT + (size_t)d*NROWS + (size_t)b*L_;
    float4 v = *(const float4*)(xp + lb*4);
    float4 p = make_float4(0.f, 0.f, 0.f, 0.f);
    if (lb > 0) p = *(const float4*)(xp + lb*4 - 4);
    float w0 = w[d*4+0], w1 = w[d*4+1], w2 = w[d*4+2], w3 = w[d*4+3];
    float bv = bias[d];
    float4 o;
    o.x = bv + p.y*w0 + p.z*w1 + p.w*w2 + v.x*w3;
    o.y = bv + p.z*w0 + p.w*w1 + v.x*w2 + v.y*w3;
    o.z = bv + p.w*w0 + v.x*w1 + v.y*w2 + v.z*w3;
    o.w = bv + v.x*w0 + v.y*w1 + v.z*w2 + v.w*w3;
    o.x = siluf(o.x); o.y = siluf(o.y); o.z = siluf(o.z); o.w = siluf(o.w);
    *(float4*)(g_uT + (size_t)d*NROWS + (size_t)b*L_ + lb*4) = o;
}

// ---------------- dt softplus, transposed out ----------------
__global__ __launch_bounds__(256) void dt2_kernel(const float* __restrict__ dtw,
                                                  const float* __restrict__ dtb) {
    __shared__ float ws[DINNER*6];
    __shared__ float bs[DINNER];
    int tid = threadIdx.x;
    int r0 = blockIdx.x * 256;
    for (int i = tid; i < DINNER*6; i += 256) ws[i] = dtw[i];
    if (tid < DINNER) bs[tid] = dtb[tid];
    __syncthreads();
    float x0 = g_xdT[0*NROWS + r0 + tid];
    float x1 = g_xdT[1*NROWS + r0 + tid];
    float x2 = g_xdT[2*NROWS + r0 + tid];
    float x3 = g_xdT[3*NROWS + r0 + tid];
    float x4 = g_xdT[4*NROWS + r0 + tid];
    float x5 = g_xdT[5*NROWS + r0 + tid];
    for (int d = 0; d < DINNER; d++) {
        float acc = bs[d];
        acc += x0*ws[d*6+0]; acc += x1*ws[d*6+1]; acc += x2*ws[d*6+2];
        acc += x3*ws[d*6+3]; acc += x4*ws[d*6+4]; acc += x5*ws[d*6+5];
        float sp = (acc > 20.f) ? acc : __logf(1.f + __expf(acc));
        g_dtT[(size_t)d*NROWS + r0 + tid] = sp;
    }
}

// ---------------- chunked selective scan ----------------
__global__ __launch_bounds__(128) void scan_phase1(const float* __restrict__ A_log) {
    int wid = (blockIdx.x * blockDim.x + threadIdx.x) >> 5;
    int lane = threadIdx.x & 31;
    int s = lane & 15, grp = lane >> 4;
    int pair = wid % 192;
    int chunk = wid / 192;
    int chan = pair*2 + grp;
    int b = chan / DINNER, d = chan % DINNER;
    float Aa = -expf(A_log[d*DSTATE + s]);
    float h = 0.f, P = 1.f;
    size_t base = (size_t)b*L_ + (size_t)chunk*CS;
    const float4* dtp = (const float4*)(g_dtT + (size_t)d*NROWS + base);
    const float4* up  = (const float4*)(g_uT  + (size_t)d*NROWS + base);
    const float4* bp  = (const float4*)(g_xdT + (size_t)(6+s)*NROWS + base);
    #pragma unroll 2
    for (int q = 0; q < CS/4; q++) {
        float4 dt4 = dtp[q], u4 = up[q], b4 = bp[q];
        float a;
        a = __expf(dt4.x*Aa); h = a*h + (dt4.x*u4.x)*b4.x; P *= a;
        a = __expf(dt4.y*Aa); h = a*h + (dt4.y*u4.y)*b4.y; P *= a;
        a = __expf(dt4.z*Aa); h = a*h + (dt4.z*u4.z)*b4.z; P *= a;
        a = __expf(dt4.w*Aa); h = a*h + (dt4.w*u4.w)*b4.w; P *= a;
    }
    int o = (chunk*384 + chan)*DSTATE + s;
    g_F[o] = h; g_P[o] = P;
}

__global__ __launch_bounds__(256) void scan_phase2() {
    int t = blockIdx.x * 256 + threadIdx.x;
    if (t >= 384*DSTATE) return;
    float H = 0.f;
    for (int j = 0; j < NC; j++) {
        int o = j*384*DSTATE + t;
        g_Hi[o] = H;
        H = g_F[o] + g_P[o]*H;
    }
}

__global__ __launch_bounds__(128) void scan_phase3(const float* __restrict__ A_log,
                                                   const float* __restrict__ Dp) {
    int wid = (blockIdx.x * blockDim.x + threadIdx.x) >> 5;
    int lane = threadIdx.x & 31;
    int s = lane & 15, grp = lane >> 4;
    int pair = wid % 192;
    int chunk = wid / 192;
    int chan = pair*2 + grp;
    int b = chan / DINNER, d = chan % DINNER;
    float Aa = -expf(A_log[d*DSTATE + s]);
    float Dpd = Dp[d];
    float h = g_Hi[(chunk*384 + chan)*DSTATE + s];
    size_t base = (size_t)b*L_ + (size_t)chunk*CS;
    const float4* dtp = (const float4*)(g_dtT + (size_t)d*NROWS + base);
    const float4* up  = (const float4*)(g_uT  + (size_t)d*NROWS + base);
    const float4* bp  = (const float4*)(g_xdT + (size_t)(6+s)*NROWS + base);
    const float4* cp  = (const float4*)(g_xdT + (size_t)(22+s)*NROWS + base);
    const float4* zp  = (const float4*)(g_xzT + (size_t)(192+d)*NROWS + base);
    float4* yp = (float4*)(g_yT + (size_t)d*NROWS + base);
    for (int q = 0; q < CS/4; q++) {
        float4 dt4 = dtp[q], u4 = up[q], b4 = bp[q], c4 = cp[q], z4 = zp[q];
        float4 yv;
        float a, p;
        a = __expf(dt4.x*Aa); h = a*h + (dt4.x*u4.x)*b4.x;
        p = h * c4.x;
        p += __shfl_xor_sync(0xffffffffu, p, 8);
        p += __shfl_xor_sync(0xffffffffu, p, 4);
        p += __shfl_xor_sync(0xffffffffu, p, 2);
        p += __shfl_xor_sync(0xffffffffu, p, 1);
        yv.x = (p + u4.x*Dpd) * siluf(z4.x);
        a = __expf(dt4.y*Aa); h = a*h + (dt4.y*u4.y)*b4.y;
        p = h * c4.y;
        p += __shfl_xor_sync(0xffffffffu, p, 8);
        p += __shfl_xor_sync(0xffffffffu, p, 4);
        p += __shfl_xor_sync(0xffffffffu, p, 2);
        p += __shfl_xor_sync(0xffffffffu, p, 1);
        yv.y = (p + u4.y*Dpd) * siluf(z4.y);
        a = __expf(dt4.z*Aa); h = a*h + (dt4.z*u4.z)*b4.z;
        p = h * c4.z;
        p += __shfl_xor_sync(0xffffffffu, p, 8);
        p += __shfl_xor_sync(0xffffffffu, p, 4);
        p += __shfl_xor_sync(0xffffffffu, p, 2);
        p += __shfl_xor_sync(0xffffffffu, p, 1);
        yv.z = (p + u4.z*Dpd) * siluf(z4.z);
        a = __expf(dt4.w*Aa); h = a*h + (dt4.w*u4.w)*b4.w;
        p = h * c4.w;
        p += __shfl_xor_sync(0xffffffffu, p, 8);
        p += __shfl_xor_sync(0xffffffffu, p, 4);
        p += __shfl_xor_sync(0xffffffffu, p, 2);
        p += __shfl_xor_sync(0xffffffffu, p, 1);
        yv.w = (p + u4.w*Dpd) * siluf(z4.w);
        if (s == 0) yp[q] = yv;
    }
}

// ---------------- residual + LayerNorm (warp per row) ----------------
__global__ __launch_bounds__(256) void ln2_kernel(const float* __restrict__ g,
                                                  const float* __restrict__ bta,
                                                  const float* __restrict__ skip) {
    int warp = (int)((blockIdx.x * blockDim.x + threadIdx.x) >> 5);
    int lane = threadIdx.x & 31;
    if (warp >= NROWS) return;
    float sk = skip[0];
    size_t base = (size_t)warp * 96;
    float t[3]; float sum = 0.f, sq = 0.f;
    #pragma unroll
    for (int i = 0; i < 3; i++) {
        int c = lane + 32*i;
        t[i] = g_outm[base+c] + sk * g_xflat[base+c];
        sum += t[i]; sq += t[i]*t[i];
    }
    #pragma unroll
    for (int k = 16; k > 0; k >>= 1) {
        sum += __shfl_xor_sync(0xffffffffu, sum, k);
        sq  += __shfl_xor_sync(0xffffffffu, sq,  k);
    }
    float mu = sum / 96.f;
    float var = sq / 96.f - mu*mu;
    float inv = rsqrtf(var + 1e-5f);
    #pragma unroll
    for (int i = 0; i < 3; i++) {
        int c = lane + 32*i;
        g_xm2[base+c] = (t[i] - mu) * inv * g[c] + bta[c];
    }
}

// ---------------- launch ----------------
extern "C" void kernel_launch(void* const* d_in, const int* in_sizes, int n_in,
                              void* d_out, int out_size) {
    const float* x     = (const float*)d_in[0];
    const float* dw_w  = (const float*)d_in[1];
    const float* dw_b  = (const float*)d_in[2];
    const float* gn_g  = (const float*)d_in[3];
    const float* gn_b  = (const float*)d_in[4];
    const float* pw1_w = (const float*)d_in[5];
    const float* pw1_b = (const float*)d_in[6];
    const float* pw2_w = (const float*)d_in[7];
    const float* pw2_b = (const float*)d_in[8];
    const float* ln_g  = (const float*)d_in[9];
    const float* ln_b  = (const float*)d_in[10];
    const float* skip  = (const float*)d_in[11];
    const float* inpw  = (const float*)d_in[12];
    const float* c1w   = (const float*)d_in[13];
    const float* c1b   = (const float*)d_in[14];
    const float* xpw   = (const float*)d_in[15];
    const float* dtw   = (const float*)d_in[16];
    const float* dtb   = (const float*)d_in[17];
    const float* A_log = (const float*)d_in[18];
    const float* Dp    = (const float*)d_in[19];
    const float* outpw = (const float*)d_in[20];
    const float* projw = (const float*)d_in[21];
    const float* projb = (const float*)d_in[22];
    float* out = (float*)d_out;

    float *p_h1, *p_h2, *p_xn, *p_xzT, *p_uT, *p_xdT, *p_yT, *p_outm, *p_xm2, *p_sc, *p_sh;
    cudaGetSymbolAddress((void**)&p_h1,   g_h1);
    cudaGetSymbolAddress((void**)&p_h2,   g_h2);
    cudaGetSymbolAddress((void**)&p_xn,   g_xn);
    cudaGetSymbolAddress((void**)&p_xzT,  g_xzT);
    cudaGetSymbolAddress((void**)&p_uT,   g_uT);
    cudaGetSymbolAddress((void**)&p_xdT,  g_xdT);
    cudaGetSymbolAddress((void**)&p_yT,   g_yT);
    cudaGetSymbolAddress((void**)&p_outm, g_outm);
    cudaGetSymbolAddress((void**)&p_xm2,  g_xm2);
    cudaGetSymbolAddress((void**)&p_sc,   g_gnsc);
    cudaGetSymbolAddress((void**)&p_sh,   g_gnsh);

    // ---- conv branch ----
    zero_stats_kernel<<<1,32>>>();
    dwconv3d_kernel<<<dim3(3,3,B_*C_), dim3(16,16)>>>(x, dw_w, dw_b);
    gn_scale_kernel<<<1,256>>>(gn_g, gn_b);
    gemmt_kernel<true,true,1,false,true><<<dim3(L_/128, 3, B_),256>>>(
        p_h1, pw1_w, pw1_b, p_h2, L_, 4*C_, C_, (size_t)C_*L_, (size_t)4*C_*L_, p_sc, p_sh);
    gemmt_kernel<true,true,0,false,false><<<dim3(L_/128, 1, B_),256>>>(
        p_h2, pw2_w, pw2_b, out, L_, C_, 4*C_, (size_t)4*C_*L_, (size_t)C_*L_, nullptr, nullptr);

    // ---- mamba branch ----
    ln1_kernel<<<dim3(L_/32, B_),256>>>(x, ln_g, ln_b);
    gemmt_kernel<false,true,0,false,false><<<dim3(NROWS/128, 3, 1),256>>>(
        p_xn, inpw, nullptr, p_xzT, NROWS, 2*DINNER, C_, 0, 0, nullptr, nullptr);
    conv1d_kernel<<<(DINNER*B_*(L_/4))/256,256>>>(c1w, c1b);
    gemmt_kernel<true,true,0,false,false><<<dim3(NROWS/128, 1, 1),256>>>(
        p_uT, xpw, nullptr, p_xdT, NROWS, 38, DINNER, 0, 0, nullptr, nullptr);
    dt2_kernel<<<NROWS/256,256>>>(dtw, dtb);
    scan_phase1<<<(192*NC)/4, 128>>>(A_log);
    scan_phase2<<<24,256>>>();
    scan_phase3<<<(192*NC)/4, 128>>>(A_log, Dp);
    gemmt_kernel<true,false,0,false,false><<<dim3(NROWS/128, 1, 1),256>>>(
        p_yT, outpw, nullptr, p_outm, NROWS, C_, DINNER, 0, 0, nullptr, nullptr);
    ln2_kernel<<<NROWS/8,256>>>(ln_g, ln_b, skip);
    gemmt_kernel<false,true,0,true,false><<<dim3(L_/128, 1, B_),256>>>(
        p_xm2, projw, projb, out, L_, C_, C_, (size_t)L_*C_, (size_t)C_*L_, nullptr, nullptr);
}

// round 8
// speedup vs baseline: 1.0095x; 1.0095x over previous
#include <cuda_runtime.h>
#include <math.h>
#include <stdint.h>

#define B_ 2
#define C_ 96
#define D_ 8
#define H_ 48
#define W_ 48
#define L_ (D_*H_*W_)          // 18432
#define NROWS (B_*L_)          // 36864
#define DSTATE 16
#define DINNER 192
#define NC 72
#define CS (L_/NC)             // 256

// ---------------- scratch ----------------
__device__ float g_h1[B_*C_*L_];
__device__ float g_h2[B_*4*C_*L_];
__device__ float g_xflat[NROWS*C_];
__device__ float g_xnT[C_*NROWS];           // LN(x) transposed [c][row]
__device__ float g_xzT[2*DINNER*NROWS];
__device__ float g_uT[DINNER*NROWS];
__device__ float g_xdT[38*NROWS];
__device__ float g_dtT[DINNER*NROWS];
__device__ float g_yT[DINNER*NROWS];
__device__ float g_outm[NROWS*C_];
__device__ float g_xm2T[C_*NROWS];          // LN2 out transposed [c][row]
__device__ float g_stats[32];
__device__ float g_gnsc[B_*C_];
__device__ float g_gnsh[B_*C_];
__device__ float g_P[NC*384*DSTATE];
__device__ float g_F[NC*384*DSTATE];
__device__ float g_Hi[NC*384*DSTATE];

__device__ __forceinline__ float siluf(float x) { return x / (1.f + __expf(-x)); }
__device__ __forceinline__ float geluf(float x) {
    return 0.5f * x * (1.f + erff(x * 0.70710678118654752f));
}
__device__ __forceinline__ unsigned f2tf(float x) {
    unsigned r;
    asm("cvt.rna.tf32.f32 %0, %1;" : "=r"(r) : "f"(x));
    return r;
}
__device__ __forceinline__ void mma_tf32(float c[4], const unsigned a[4], const unsigned b[2]) {
    asm("mma.sync.aligned.m16n8k8.row.col.f32.tf32.tf32.f32 "
        "{%0,%1,%2,%3}, {%4,%5,%6,%7}, {%8,%9}, {%0,%1,%2,%3};"
        : "+f"(c[0]), "+f"(c[1]), "+f"(c[2]), "+f"(c[3])
        : "r"(a[0]), "r"(a[1]), "r"(a[2]), "r"(a[3]), "r"(b[0]), "r"(b[1]));
}
__device__ __forceinline__ void cpa16(uint32_t dst, const float* src) {
    asm volatile("cp.async.cg.shared.global [%0], [%1], 16;" :: "r"(dst), "l"(src));
}
__device__ __forceinline__ void cpa16z(uint32_t dst, const float* src) {
    asm volatile("cp.async.cg.shared.global [%0], [%1], 16, 0;" :: "r"(dst), "l"(src));
}

// ---------------- depthwise conv3d + bias + fused GN stats ----------------
__global__ __launch_bounds__(256) void dwconv3d_kernel(const float* __restrict__ x,
                                                       const float* __restrict__ w,
                                                       const float* __restrict__ bias) {
    __shared__ float s[10][22][22];
    __shared__ float wsm[147];
    __shared__ float r1[8], r2[8];
    int bc = blockIdx.z;
    int c = bc % C_;
    int b = bc / C_;
    int h0 = blockIdx.y * 16, w0 = blockIdx.x * 16;
    int tid = threadIdx.y * 16 + threadIdx.x;
    const float* xp = x + (size_t)bc * L_;
    for (int i = tid; i < 147; i += 256) wsm[i] = w[c*147 + i];
    for (int i = tid; i < 10*22*22; i += 256) {
        int dd = i / 484; int r = i % 484; int hh = r / 22; int ww = r % 22;
        int d = dd - 1, h = h0 + hh - 3, wq = w0 + ww - 3;
        float v = 0.f;
        if (d >= 0 && d < D_ && h >= 0 && h < H_ && wq >= 0 && wq < W_)
            v = xp[(d*H_ + h)*W_ + wq];
        s[dd][hh][ww] = v;
    }
    __syncthreads();
    int ty = threadIdx.y, tx = threadIdx.x;
    float bv = bias[c];
    float acc[8];
    #pragma unroll
    for (int i = 0; i < 8; i++) acc[i] = bv;
    #pragma unroll
    for (int dd = 0; dd < 10; dd++) {
        #pragma unroll
        for (int kh = 0; kh < 7; kh++) {
            #pragma unroll
            for (int kw = 0; kw < 7; kw++) {
                float v = s[dd][ty+kh][tx+kw];
                #pragma unroll
                for (int kd = 0; kd < 3; kd++) {
                    int od = dd - kd;
                    if (od >= 0 && od < 8)
                        acc[od] += v * wsm[kd*49 + kh*7 + kw];
                }
            }
        }
    }
    size_t base = (size_t)bc * L_;
    float s1 = 0.f, s2 = 0.f;
    #pragma unroll
    for (int od = 0; od < 8; od++) {
        g_h1[base + (od*H_ + h0 + ty)*W_ + (w0 + tx)] = acc[od];
        s1 += acc[od]; s2 += acc[od]*acc[od];
    }
    #pragma unroll
    for (int k = 16; k > 0; k >>= 1) {
        s1 += __shfl_xor_sync(0xffffffffu, s1, k);
        s2 += __shfl_xor_sync(0xffffffffu, s2, k);
    }
    if ((tid & 31) == 0) { r1[tid >> 5] = s1; r2[tid >> 5] = s2; }
    __syncthreads();
    if (tid == 0) {
        float t1 = 0.f, t2 = 0.f;
        #pragma unroll
        for (int i = 0; i < 8; i++) { t1 += r1[i]; t2 += r2[i]; }
        int z = b*8 + c/12;
        atomicAdd(&g_stats[z*2], t1);
        atomicAdd(&g_stats[z*2+1], t2);
    }
}

__global__ void zero_stats_kernel() { if (threadIdx.x < 32) g_stats[threadIdx.x] = 0.f; }

__global__ void gn_scale_kernel(const float* __restrict__ gg, const float* __restrict__ gb) {
    int i = threadIdx.x;
    if (i >= B_*C_) return;
    int b = i / C_, c = i % C_;
    int z = b*8 + c/12;
    float cnt = 12.f * (float)L_;
    float mu = g_stats[z*2] / cnt;
    float var = g_stats[z*2+1] / cnt - mu*mu;
    float inv = rsqrtf(var + 1e-5f);
    g_gnsc[i] = inv * gg[c];
    g_gnsh[i] = gb[c] - mu * inv * gg[c];
}

// ---------------- GEMM v6: tf32 mma + cp.async double-buffer ----------------
// A stored [K, lda-major] (K-major). OUT_NM: C stored [N, M]; else [M, N].
// ACT: 0 none, 1 gelu.  ACC: += into C.  NORM: per-k scale/shift applied post-LDS.
template<bool OUT_NM, int ACT, bool ACC, bool NORM>
__global__ __launch_bounds__(256, 2) void gemmt_kernel(
    const float* __restrict__ A, int lda, size_t aBatch,
    const float* __restrict__ Wt,
    const float* __restrict__ bias, float* __restrict__ Co,
    int M, int N, int K, size_t cBatch,
    const float* __restrict__ nscB, const float* __restrict__ nshB)
{
    __shared__ float As[2][16][132];
    __shared__ float Ws[2][128][28];
    int m0 = blockIdx.x * 128, n0 = blockIdx.y * 128;
    A  += (size_t)blockIdx.z * aBatch;
    Co += (size_t)blockIdx.z * cBatch;
    const float* nsc = NORM ? (nscB + blockIdx.z * C_) : nullptr;
    const float* nsh = NORM ? (nshB + blockIdx.z * C_) : nullptr;
    int tid = threadIdx.x;
    int lane = tid & 31;
    int warp = tid >> 5;
    int wm = (warp & 1) * 64;
    int wn = (warp >> 1) * 32;
    int r = lane >> 2, cq = lane & 3;

    // copy assignments
    int a_kk0 = tid >> 5,        a_ch0 = (tid & 31) << 2;       // + t*8 rows
    int w_nn0 = tid >> 2,        w_ck0 = (tid & 3) << 2;        // + t*64 rows
    uint32_t as_sm = (uint32_t)__cvta_generic_to_shared(&As[0][0][0]);
    uint32_t ws_sm = (uint32_t)__cvta_generic_to_shared(&Ws[0][0][0]);

    float cacc[4][4][4];
    #pragma unroll
    for (int mt = 0; mt < 4; mt++)
        #pragma unroll
        for (int nt = 0; nt < 4; nt++)
            #pragma unroll
            for (int e = 0; e < 4; e++) cacc[mt][nt][e] = 0.f;

    int niter = K >> 4;
    // issue tile 0
    {
        #pragma unroll
        for (int t = 0; t < 2; t++) {
            int kk = a_kk0 + t*8;
            cpa16(as_sm + (kk*132 + a_ch0)*4, A + (size_t)kk*lda + m0 + a_ch0);
            int nn = w_nn0 + t*64;
            uint32_t wd = ws_sm + (nn*28 + w_ck0)*4;
            const float* wsrc = Wt + (size_t)(n0+nn)*K + w_ck0;
            if (n0 + nn < N) cpa16(wd, wsrc); else cpa16z(wd, Wt);
        }
        asm volatile("cp.async.commit_group;");
    }

    for (int i = 0; i < niter; i++) {
        int buf = i & 1;
        if (i + 1 < niter) {
            int nb = (i+1) & 1;
            int k0 = (i+1) << 4;
            uint32_t asb = as_sm + nb*(16*132*4);
            uint32_t wsb = ws_sm + nb*(128*28*4);
            #pragma unroll
            for (int t = 0; t < 2; t++) {
                int kk = a_kk0 + t*8;
                cpa16(asb + (kk*132 + a_ch0)*4, A + (size_t)(k0+kk)*lda + m0 + a_ch0);
                int nn = w_nn0 + t*64;
                uint32_t wd = wsb + (nn*28 + w_ck0)*4;
                const float* wsrc = Wt + (size_t)(n0+nn)*K + k0 + w_ck0;
                if (n0 + nn < N) cpa16(wd, wsrc); else cpa16z(wd, Wt);
            }
            asm volatile("cp.async.commit_group;");
            asm volatile("cp.async.wait_group 1;");
        } else {
            asm volatile("cp.async.wait_group 0;");
        }
        __syncthreads();

        int kbase = i << 4;
        #pragma unroll
        for (int ks = 0; ks < 2; ks++) {
            int k_lo = ks*8 + cq;
            float sc0 = 1.f, sh0 = 0.f, sc1 = 1.f, sh1 = 0.f;
            if (NORM) {
                sc0 = __ldg(&nsc[kbase + k_lo]);     sh0 = __ldg(&nsh[kbase + k_lo]);
                sc1 = __ldg(&nsc[kbase + k_lo + 4]); sh1 = __ldg(&nsh[kbase + k_lo + 4]);
            }
            unsigned af[4][4];
            #pragma unroll
            for (int mt = 0; mt < 4; mt++) {
                int mb = wm + mt*16 + r;
                float a0 = As[buf][k_lo    ][mb];
                float a1 = As[buf][k_lo    ][mb + 8];
                float a2 = As[buf][k_lo + 4][mb];
                float a3 = As[buf][k_lo + 4][mb + 8];
                if (NORM) {
                    a0 = a0*sc0 + sh0; a1 = a1*sc0 + sh0;
                    a2 = a2*sc1 + sh1; a3 = a3*sc1 + sh1;
                }
                af[mt][0] = f2tf(a0); af[mt][1] = f2tf(a1);
                af[mt][2] = f2tf(a2); af[mt][3] = f2tf(a3);
            }
            unsigned bf[4][2];
            #pragma unroll
            for (int nt = 0; nt < 4; nt++) {
                int nb = wn + nt*8 + r;
                bf[nt][0] = f2tf(Ws[buf][nb][k_lo]);
                bf[nt][1] = f2tf(Ws[buf][nb][k_lo + 4]);
            }
            #pragma unroll
            for (int mt = 0; mt < 4; mt++)
                #pragma unroll
                for (int nt = 0; nt < 4; nt++)
                    mma_tf32(cacc[mt][nt], af[mt], bf[nt]);
        }
        __syncthreads();
    }

    // ---- epilogue ----
    int er = lane >> 2, j2 = (lane & 3) * 2;
    #pragma unroll
    for (int mt = 0; mt < 4; mt++)
        #pragma unroll
        for (int nt = 0; nt < 4; nt++) {
            int mb = m0 + wm + mt*16 + er;
            int nb = n0 + wn + nt*8 + j2;
            #pragma unroll
            for (int e = 0; e < 4; e++) {
                int m = mb + ((e >> 1) ? 8 : 0);
                int n = nb + (e & 1);
                if (n < N) {
                    float v = cacc[mt][nt][e] + (bias ? bias[n] : 0.f);
                    if (ACT == 1) v = geluf(v);
                    size_t off = OUT_NM ? ((size_t)n*M + m) : ((size_t)m*N + n);
                    if (ACC) v += Co[off];
                    Co[off] = v;
                }
            }
        }
}

// ---------------- LayerNorm1 over C with transpose (writes xflat row-major, xnT) -----
__global__ __launch_bounds__(256) void ln1_kernel(const float* __restrict__ x,
                                                  const float* __restrict__ g,
                                                  const float* __restrict__ bta) {
    __shared__ float s[96][33];
    __shared__ float mu_s[32], rs_s[32];
    int b = blockIdx.y;
    int l0 = blockIdx.x * 32;
    int tid = threadIdx.x;
    int tx = tid & 31, ty = tid >> 5;
    const float* xp = x + (size_t)b * C_ * L_;
    for (int c = ty; c < C_; c += 8)
        s[c][tx] = xp[(size_t)c * L_ + l0 + tx];
    __syncthreads();
    if (tid < 32) {
        float sum = 0.f, sq = 0.f;
        #pragma unroll 4
        for (int c = 0; c < C_; c++) { float v = s[c][tid]; sum += v; sq += v*v; }
        float mu = sum / 96.f;
        float var = sq / 96.f - mu*mu;
        mu_s[tid] = mu; rs_s[tid] = rsqrtf(var + 1e-5f);
    }
    __syncthreads();
    // xflat row-major (c fastest => coalesced)
    for (int idx = tid; idx < 96*32; idx += 256) {
        int c = idx % 96, l = idx / 96;
        g_xflat[(size_t)(b*L_ + l0 + l)*96 + c] = s[c][l];
    }
    // xnT transposed (l fastest => coalesced)
    for (int idx = tid; idx < 96*32; idx += 256) {
        int l = idx & 31, c = idx >> 5;
        float v = s[c][l];
        g_xnT[(size_t)c*NROWS + b*L_ + l0 + l] = (v - mu_s[l]) * rs_s[l] * g[c] + bta[c];
    }
}

// ---------------- causal depthwise conv1d (k=4) + SiLU ----------------
__global__ __launch_bounds__(256) void conv1d_kernel(const float* __restrict__ w,
                                                     const float* __restrict__ bias) {
    int idx = blockIdx.x * 256 + threadIdx.x;
    int lb = idx % (L_/4);
    int db = idx / (L_/4);
    if (db >= DINNER * B_) return;
    int b = db % B_, d = db / B_;
    const float* xp = g_xzT + (size_t)d*NROWS + (size_t)b*L_;
    float4 v = *(const float4*)(xp + lb*4);
    float4 p = make_float4(0.f, 0.f, 0.f, 0.f);
    if (lb > 0) p = *(const float4*)(xp + lb*4 - 4);
    float w0 = w[d*4+0], w1 = w[d*4+1], w2 = w[d*4+2], w3 = w[d*4+3];
    float bv = bias[d];
    float4 o;
    o.x = bv + p.y*w0 + p.z*w1 + p.w*w2 + v.x*w3;
    o.y = bv + p.z*w0 + p.w*w1 + v.x*w2 + v.y*w3;
    o.z = bv + p.w*w0 + v.x*w1 + v.y*w2 + v.z*w3;
    o.w = bv + v.x*w0 + v.y*w1 + v.z*w2 + v.w*w3;
    o.x = siluf(o.x); o.y = siluf(o.y); o.z = siluf(o.z); o.w = siluf(o.w);
    *(float4*)(g_uT + (size_t)d*NROWS + (size_t)b*L_ + lb*4) = o;
}

// ---------------- dt softplus, transposed out ----------------
__global__ __launch_bounds__(256) void dt2_kernel(const float* __restrict__ dtw,
                                                  const float* __restrict__ dtb) {
    __shared__ float ws[DINNER*6];
    __shared__ float bs[DINNER];
    int tid = threadIdx.x;
    int r0 = blockIdx.x * 256;
    for (int i = tid; i < DINNER*6; i += 256) ws[i] = dtw[i];
    if (tid < DINNER) bs[tid] = dtb[tid];
    __syncthreads();
    float x0 = g_xdT[0*NROWS + r0 + tid];
    float x1 = g_xdT[1*NROWS + r0 + tid];
    float x2 = g_xdT[2*NROWS + r0 + tid];
    float x3 = g_xdT[3*NROWS + r0 + tid];
    float x4 = g_xdT[4*NROWS + r0 + tid];
    float x5 = g_xdT[5*NROWS + r0 + tid];
    for (int d = 0; d < DINNER; d++) {
        float acc = bs[d];
        acc += x0*ws[d*6+0]; acc += x1*ws[d*6+1]; acc += x2*ws[d*6+2];
        acc += x3*ws[d*6+3]; acc += x4*ws[d*6+4]; acc += x5*ws[d*6+5];
        float sp = (acc > 20.f) ? acc : __logf(1.f + __expf(acc));
        g_dtT[(size_t)d*NROWS + r0 + tid] = sp;
    }
}

// ---------------- chunked selective scan ----------------
__global__ __launch_bounds__(128) void scan_phase1(const float* __restrict__ A_log) {
    int wid = (blockIdx.x * blockDim.x + threadIdx.x) >> 5;
    int lane = threadIdx.x & 31;
    int s = lane & 15, grp = lane >> 4;
    int pair = wid % 192;
    int chunk = wid / 192;
    int chan = pair*2 + grp;
    int b = chan / DINNER, d = chan % DINNER;
    float Aa = -expf(A_log[d*DSTATE + s]);
    float h = 0.f, P = 1.f;
    size_t base = (size_t)b*L_ + (size_t)chunk*CS;
    const float4* dtp = (const float4*)(g_dtT + (size_t)d*NROWS + base);
    const float4* up  = (const float4*)(g_uT  + (size_t)d*NROWS + base);
    const float4* bp  = (const float4*)(g_xdT + (size_t)(6+s)*NROWS + base);
    #pragma unroll 2
    for (int q = 0; q < CS/4; q++) {
        float4 dt4 = dtp[q], u4 = up[q], b4 = bp[q];
        float a;
        a = __expf(dt4.x*Aa); h = a*h + (dt4.x*u4.x)*b4.x; P *= a;
        a = __expf(dt4.y*Aa); h = a*h + (dt4.y*u4.y)*b4.y; P *= a;
        a = __expf(dt4.z*Aa); h = a*h + (dt4.z*u4.z)*b4.z; P *= a;
        a = __expf(dt4.w*Aa); h = a*h + (dt4.w*u4.w)*b4.w; P *= a;
    }
    int o = (chunk*384 + chan)*DSTATE + s;
    g_F[o] = h; g_P[o] = P;
}

__global__ __launch_bounds__(256) void scan_phase2() {
    int t = blockIdx.x * 256 + threadIdx.x;
    if (t >= 384*DSTATE) return;
    float H = 0.f;
    for (int j = 0; j < NC; j++) {
        int o = j*384*DSTATE + t;
        g_Hi[o] = H;
        H = g_F[o] + g_P[o]*H;
    }
}

__global__ __launch_bounds__(128) void scan_phase3(const float* __restrict__ A_log,
                                                   const float* __restrict__ Dp) {
    int wid = (blockIdx.x * blockDim.x + threadIdx.x) >> 5;
    int lane = threadIdx.x & 31;
    int s = lane & 15, grp = lane >> 4;
    int pair = wid % 192;
    int chunk = wid / 192;
    int chan = pair*2 + grp;
    int b = chan / DINNER, d = chan % DINNER;
    float Aa = -expf(A_log[d*DSTATE + s]);
    float Dpd = Dp[d];
    float h = g_Hi[(chunk*384 + chan)*DSTATE + s];
    size_t base = (size_t)b*L_ + (size_t)chunk*CS;
    const float4* dtp = (const float4*)(g_dtT + (size_t)d*NROWS + base);
    const float4* up  = (const float4*)(g_uT  + (size_t)d*NROWS + base);
    const float4* bp  = (const float4*)(g_xdT + (size_t)(6+s)*NROWS + base);
    const float4* cp  = (const float4*)(g_xdT + (size_t)(22+s)*NROWS + base);
    const float4* zp  = (const float4*)(g_xzT + (size_t)(192+d)*NROWS + base);
    float4* yp = (float4*)(g_yT + (size_t)d*NROWS + base);
    for (int q = 0; q < CS/4; q++) {
        float4 dt4 = dtp[q], u4 = up[q], b4 = bp[q], c4 = cp[q], z4 = zp[q];
        float4 yv;
        float a, p;
        a = __expf(dt4.x*Aa); h = a*h + (dt4.x*u4.x)*b4.x;
        p = h * c4.x;
        p += __shfl_xor_sync(0xffffffffu, p, 8);
        p += __shfl_xor_sync(0xffffffffu, p, 4);
        p += __shfl_xor_sync(0xffffffffu, p, 2);
        p += __shfl_xor_sync(0xffffffffu, p, 1);
        yv.x = (p + u4.x*Dpd) * siluf(z4.x);
        a = __expf(dt4.y*Aa); h = a*h + (dt4.y*u4.y)*b4.y;
        p = h * c4.y;
        p += __shfl_xor_sync(0xffffffffu, p, 8);
        p += __shfl_xor_sync(0xffffffffu, p, 4);
        p += __shfl_xor_sync(0xffffffffu, p, 2);
        p += __shfl_xor_sync(0xffffffffu, p, 1);
        yv.y = (p + u4.y*Dpd) * siluf(z4.y);
        a = __expf(dt4.z*Aa); h = a*h + (dt4.z*u4.z)*b4.z;
        p = h * c4.z;
        p += __shfl_xor_sync(0xffffffffu, p, 8);
        p += __shfl_xor_sync(0xffffffffu, p, 4);
        p += __shfl_xor_sync(0xffffffffu, p, 2);
        p += __shfl_xor_sync(0xffffffffu, p, 1);
        yv.z = (p + u4.z*Dpd) * siluf(z4.z);
        a = __expf(dt4.w*Aa); h = a*h + (dt4.w*u4.w)*b4.w;
        p = h * c4.w;
        p += __shfl_xor_sync(0xffffffffu, p, 8);
        p += __shfl_xor_sync(0xffffffffu, p, 4);
        p += __shfl_xor_sync(0xffffffffu, p, 2);
        p += __shfl_xor_sync(0xffffffffu, p, 1);
        yv.w = (p + u4.w*Dpd) * siluf(z4.w);
        if (s == 0) yp[q] = yv;
    }
}

// ---------------- residual + LayerNorm2, tiled, transposed output ----------------
__global__ __launch_bounds__(256) void ln2_kernel(const float* __restrict__ g,
                                                  const float* __restrict__ bta,
                                                  const float* __restrict__ skip) {
    __shared__ float s[96][33];
    __shared__ float mu_s[32], rs_s[32];
    int r0 = blockIdx.x * 32;
    int tid = threadIdx.x;
    float sk = skip[0];
    for (int idx = tid; idx < 96*32; idx += 256) {
        int c = idx % 96, l = idx / 96;
        size_t off = (size_t)(r0 + l)*96 + c;
        s[c][l] = g_outm[off] + sk * g_xflat[off];
    }
    __syncthreads();
    if (tid < 32) {
        float sum = 0.f, sq = 0.f;
        #pragma unroll 4
        for (int c = 0; c < C_; c++) { float v = s[c][tid]; sum += v; sq += v*v; }
        float mu = sum / 96.f;
        float var = sq / 96.f - mu*mu;
        mu_s[tid] = mu; rs_s[tid] = rsqrtf(var + 1e-5f);
    }
    __syncthreads();
    for (int idx = tid; idx < 96*32; idx += 256) {
        int l = idx & 31, c = idx >> 5;
        float v = s[c][l];
        g_xm2T[(size_t)c*NROWS + r0 + l] = (v - mu_s[l]) * rs_s[l] * g[c] + bta[c];
    }
}

// ---------------- launch ----------------
extern "C" void kernel_launch(void* const* d_in, const int* in_sizes, int n_in,
                              void* d_out, int out_size) {
    const float* x     = (const float*)d_in[0];
    const float* dw_w  = (const float*)d_in[1];
    const float* dw_b  = (const float*)d_in[2];
    const float* gn_g  = (const float*)d_in[3];
    const float* gn_b  = (const float*)d_in[4];
    const float* pw1_w = (const float*)d_in[5];
    const float* pw1_b = (const float*)d_in[6];
    const float* pw2_w = (const float*)d_in[7];
    const float* pw2_b = (const float*)d_in[8];
    const float* ln_g  = (const float*)d_in[9];
    const float* ln_b  = (const float*)d_in[10];
    const float* skip  = (const float*)d_in[11];
    const float* inpw  = (const float*)d_in[12];
    const float* c1w   = (const float*)d_in[13];
    const float* c1b   = (const float*)d_in[14];
    const float* xpw   = (const float*)d_in[15];
    const float* dtw   = (const float*)d_in[16];
    const float* dtb   = (const float*)d_in[17];
    const float* A_log = (const float*)d_in[18];
    const float* Dp    = (const float*)d_in[19];
    const float* outpw = (const float*)d_in[20];
    const float* projw = (const float*)d_in[21];
    const float* projb = (const float*)d_in[22];
    float* out = (float*)d_out;

    float *p_h1, *p_h2, *p_xnT, *p_xzT, *p_uT, *p_xdT, *p_yT, *p_outm, *p_xm2T, *p_sc, *p_sh;
    cudaGetSymbolAddress((void**)&p_h1,   g_h1);
    cudaGetSymbolAddress((void**)&p_h2,   g_h2);
    cudaGetSymbolAddress((void**)&p_xnT,  g_xnT);
    cudaGetSymbolAddress((void**)&p_xzT,  g_xzT);
    cudaGetSymbolAddress((void**)&p_uT,   g_uT);
    cudaGetSymbolAddress((void**)&p_xdT,  g_xdT);
    cudaGetSymbolAddress((void**)&p_yT,   g_yT);
    cudaGetSymbolAddress((void**)&p_outm, g_outm);
    cudaGetSymbolAddress((void**)&p_xm2T, g_xm2T);
    cudaGetSymbolAddress((void**)&p_sc,   g_gnsc);
    cudaGetSymbolAddress((void**)&p_sh,   g_gnsh);

    // ---- conv branch ----
    zero_stats_kernel<<<1,32>>>();
    dwconv3d_kernel<<<dim3(3,3,B_*C_), dim3(16,16)>>>(x, dw_w, dw_b);
    gn_scale_kernel<<<1,256>>>(gn_g, gn_b);
    // pw1: gelu(W1 @ gn(h1)) -> h2 [b][o][l]
    gemmt_kernel<true,1,false,true><<<dim3(L_/128, 3, B_),256>>>(
        p_h1, L_, (size_t)C_*L_, pw1_w, pw1_b, p_h2, L_, 4*C_, C_, (size_t)4*C_*L_, p_sc, p_sh);
    // pw2 -> conv_out into d_out
    gemmt_kernel<true,0,false,false><<<dim3(L_/128, 1, B_),256>>>(
        p_h2, L_, (size_t)4*C_*L_, pw2_w, pw2_b, out, L_, C_, 4*C_, (size_t)C_*L_, nullptr, nullptr);

    // ---- mamba branch ----
    ln1_kernel<<<dim3(L_/32, B_),256>>>(x, ln_g, ln_b);
    // in_proj: A = xnT [96][NROWS] -> xzT [384][NROWS]
    gemmt_kernel<true,0,false,false><<<dim3(NROWS/128, 3, 1),256>>>(
        p_xnT, NROWS, 0, inpw, nullptr, p_xzT, NROWS, 2*DINNER, C_, 0, nullptr, nullptr);
    conv1d_kernel<<<(DINNER*B_*(L_/4))/256,256>>>(c1w, c1b);
    // x_proj: A = uT [192][NROWS] -> xdT [38][NROWS]
    gemmt_kernel<true,0,false,false><<<dim3(NROWS/128, 1, 1),256>>>(
        p_uT, NROWS, 0, xpw, nullptr, p_xdT, NROWS, 38, DINNER, 0, nullptr, nullptr);
    dt2_kernel<<<NROWS/256,256>>>(dtw, dtb);
    scan_phase1<<<(192*NC)/4, 128>>>(A_log);
    scan_phase2<<<24,256>>>();
    scan_phase3<<<(192*NC)/4, 128>>>(A_log, Dp);
    // out_proj: A = yT [192][NROWS] -> outm [row][96]
    gemmt_kernel<false,0,false,false><<<dim3(NROWS/128, 1, 1),256>>>(
        p_yT, NROWS, 0, outpw, nullptr, p_outm, NROWS, C_, DINNER, 0, nullptr, nullptr);
    ln2_kernel<<<NROWS/32,256>>>(ln_g, ln_b, skip);
    // proj: A = xm2T [96][NROWS] (per-batch column slice), accumulate into d_out
    gemmt_kernel<true,0,true,false><<<dim3(L_/128, 1, B_),256>>>(
        p_xm2T, NROWS, (size_t)L_, projw, projb, out, L_, C_, C_, (size_t)C_*L_, nullptr, nullptr);
}

// round 9
// speedup vs baseline: 1.0400x; 1.0302x over previous
#include <cuda_runtime.h>
#include <math.h>
#include <stdint.h>

#define B_ 2
#define C_ 96
#define D_ 8
#define H_ 48
#define W_ 48
#define L_ (D_*H_*W_)          // 18432
#define NROWS (B_*L_)          // 36864
#define DSTATE 16
#define DINNER 192
#define NC 72
#define CS (L_/NC)             // 256

// GEMM smem pool sizing (floats): 3 A-bufs [16][136] + 3 W-bufs [128][28]
#define A_BUF (16*136)         // 2176
#define W_BUF (128*28)         // 3584
#define POOL_FLOATS (3*A_BUF + 3*W_BUF)   // 17280
#define POOL_BYTES (POOL_FLOATS*4)        // 69120

// ---------------- scratch ----------------
__device__ float g_h1[B_*C_*L_];
__device__ float g_h2[B_*4*C_*L_];
__device__ float g_xflat[NROWS*C_];
__device__ float g_xnT[C_*NROWS];
__device__ float g_xzT[2*DINNER*NROWS];
__device__ float g_uT[DINNER*NROWS];
__device__ float g_xdT[38*NROWS];
__device__ float g_dtT[DINNER*NROWS];
__device__ float g_yT[DINNER*NROWS];
__device__ float g_xm2T[C_*NROWS];
__device__ float g_stats[32];
__device__ float g_gnsc[B_*C_];
__device__ float g_gnsh[B_*C_];
__device__ float g_P[NC*384*DSTATE];
__device__ float g_F[NC*384*DSTATE];
__device__ float g_Hi[NC*384*DSTATE];

__device__ __forceinline__ float siluf(float x) { return x / (1.f + __expf(-x)); }
__device__ __forceinline__ float geluf(float x) {
    return 0.5f * x * (1.f + erff(x * 0.70710678118654752f));
}
__device__ __forceinline__ void mma_tf32(float c[4], const unsigned a[4], const unsigned b[2]) {
    asm("mma.sync.aligned.m16n8k8.row.col.f32.tf32.tf32.f32 "
        "{%0,%1,%2,%3}, {%4,%5,%6,%7}, {%8,%9}, {%0,%1,%2,%3};"
        : "+f"(c[0]), "+f"(c[1]), "+f"(c[2]), "+f"(c[3])
        : "r"(a[0]), "r"(a[1]), "r"(a[2]), "r"(a[3]), "r"(b[0]), "r"(b[1]));
}
__device__ __forceinline__ void cpa16(uint32_t dst, const float* src) {
    asm volatile("cp.async.cg.shared.global [%0], [%1], 16;" :: "r"(dst), "l"(src));
}
__device__ __forceinline__ void cpa16z(uint32_t dst, const float* src) {
    asm volatile("cp.async.cg.shared.global [%0], [%1], 16, 0;" :: "r"(dst), "l"(src));
}

// ---------------- depthwise conv3d + bias + fused GN stats ----------------
__global__ __launch_bounds__(256) void dwconv3d_kernel(const float* __restrict__ x,
                                                       const float* __restrict__ w,
                                                       const float* __restrict__ bias) {
    __shared__ float s[10][22][22];
    __shared__ float wsm[147];
    __shared__ float r1[8], r2[8];
    int bc = blockIdx.z;
    int c = bc % C_;
    int b = bc / C_;
    int h0 = blockIdx.y * 16, w0 = blockIdx.x * 16;
    int tid = threadIdx.y * 16 + threadIdx.x;
    const float* xp = x + (size_t)bc * L_;
    for (int i = tid; i < 147; i += 256) wsm[i] = w[c*147 + i];
    for (int i = tid; i < 10*22*22; i += 256) {
        int dd = i / 484; int r = i % 484; int hh = r / 22; int ww = r % 22;
        int d = dd - 1, h = h0 + hh - 3, wq = w0 + ww - 3;
        float v = 0.f;
        if (d >= 0 && d < D_ && h >= 0 && h < H_ && wq >= 0 && wq < W_)
            v = xp[(d*H_ + h)*W_ + wq];
        s[dd][hh][ww] = v;
    }
    __syncthreads();
    int ty = threadIdx.y, tx = threadIdx.x;
    float bv = bias[c];
    float acc[8];
    #pragma unroll
    for (int i = 0; i < 8; i++) acc[i] = bv;
    #pragma unroll
    for (int dd = 0; dd < 10; dd++) {
        #pragma unroll
        for (int kh = 0; kh < 7; kh++) {
            #pragma unroll
            for (int kw = 0; kw < 7; kw++) {
                float v = s[dd][ty+kh][tx+kw];
                #pragma unroll
                for (int kd = 0; kd < 3; kd++) {
                    int od = dd - kd;
                    if (od >= 0 && od < 8)
                        acc[od] += v * wsm[kd*49 + kh*7 + kw];
                }
            }
        }
    }
    size_t base = (size_t)bc * L_;
    float s1 = 0.f, s2 = 0.f;
    #pragma unroll
    for (int od = 0; od < 8; od++) {
        g_h1[base + (od*H_ + h0 + ty)*W_ + (w0 + tx)] = acc[od];
        s1 += acc[od]; s2 += acc[od]*acc[od];
    }
    #pragma unroll
    for (int k = 16; k > 0; k >>= 1) {
        s1 += __shfl_xor_sync(0xffffffffu, s1, k);
        s2 += __shfl_xor_sync(0xffffffffu, s2, k);
    }
    if ((tid & 31) == 0) { r1[tid >> 5] = s1; r2[tid >> 5] = s2; }
    __syncthreads();
    if (tid == 0) {
        float t1 = 0.f, t2 = 0.f;
        #pragma unroll
        for (int i = 0; i < 8; i++) { t1 += r1[i]; t2 += r2[i]; }
        int z = b*8 + c/12;
        atomicAdd(&g_stats[z*2], t1);
        atomicAdd(&g_stats[z*2+1], t2);
    }
}

__global__ void zero_stats_kernel() { if (threadIdx.x < 32) g_stats[threadIdx.x] = 0.f; }

__global__ void gn_scale_kernel(const float* __restrict__ gg, const float* __restrict__ gb) {
    int i = threadIdx.x;
    if (i >= B_*C_) return;
    int b = i / C_, c = i % C_;
    int z = b*8 + c/12;
    float cnt = 12.f * (float)L_;
    float mu = g_stats[z*2] / cnt;
    float var = g_stats[z*2+1] / cnt - mu*mu;
    float inv = rsqrtf(var + 1e-5f);
    g_gnsc[i] = inv * gg[c];
    g_gnsh[i] = gb[c] - mu * inv * gg[c];
}

// ---------------- GEMM v7: tf32 mma, 3-stage cp.async, no CVT, conflict-free smem ----
// A stored K-major [K][lda]. OUT_NM: C[N][M]; else C[M][N].
// FUSE=1: out_proj + residual + LN2 fused epilogue (OUT_NM/ACT/ACC ignored; N must be <=128 per block).
template<bool OUT_NM, int ACT, bool ACC, bool NORM, int FUSE>
__global__ __launch_bounds__(256, 2) void gemmt_kernel(
    const float* __restrict__ A, int lda, size_t aBatch,
    const float* __restrict__ Wt,
    const float* __restrict__ bias, float* __restrict__ Co,
    int M, int N, int K, size_t cBatch,
    const float* __restrict__ nscB, const float* __restrict__ nshB,
    const float* __restrict__ ln_g, const float* __restrict__ ln_b,
    const float* __restrict__ skipp, const float* __restrict__ xflat)
{
    extern __shared__ float pool[];
    float* Asm = pool;                      // [3][16][136]
    float* Wsm = pool + 3*A_BUF;            // [3][128][28]
    int m0 = blockIdx.x * 128, n0 = blockIdx.y * 128;
    A  += (size_t)blockIdx.z * aBatch;
    Co += (size_t)blockIdx.z * cBatch;
    const float* nsc = NORM ? (nscB + blockIdx.z * C_) : nullptr;
    const float* nsh = NORM ? (nshB + blockIdx.z * C_) : nullptr;
    int tid = threadIdx.x;
    int lane = tid & 31;
    int warp = tid >> 5;
    int wm = (warp & 1) * 64;
    int wn = (warp >> 1) * 32;
    int r = lane >> 2, cq = lane & 3;

    int a_kk0 = tid >> 5,  a_ch0 = (tid & 31) << 2;
    int w_nn0 = tid >> 2,  w_ck0 = (tid & 3) << 2;
    uint32_t as_sm = (uint32_t)__cvta_generic_to_shared(Asm);
    uint32_t ws_sm = (uint32_t)__cvta_generic_to_shared(Wsm);

    float cacc[4][4][4];
    #pragma unroll
    for (int mt = 0; mt < 4; mt++)
        #pragma unroll
        for (int nt = 0; nt < 4; nt++)
            #pragma unroll
            for (int e = 0; e < 4; e++) cacc[mt][nt][e] = 0.f;

    int niter = K >> 4;
    // prologue: issue tiles 0, 1
    #pragma unroll
    for (int pi = 0; pi < 2; pi++) {
        int k0 = pi << 4;
        uint32_t asb = as_sm + pi*(A_BUF*4);
        uint32_t wsb = ws_sm + pi*(W_BUF*4);
        #pragma unroll
        for (int t = 0; t < 2; t++) {
            int kk = a_kk0 + t*8;
            cpa16(asb + (kk*136 + a_ch0)*4, A + (size_t)(k0+kk)*lda + m0 + a_ch0);
            int nn = w_nn0 + t*64;
            uint32_t wd = wsb + (nn*28 + w_ck0)*4;
            if (n0 + nn < N) cpa16(wd, Wt + (size_t)(n0+nn)*K + k0 + w_ck0);
            else             cpa16z(wd, Wt);
        }
        asm volatile("cp.async.commit_group;");
    }

    for (int i = 0; i < niter; i++) {
        if (i + 1 < niter) asm volatile("cp.async.wait_group 1;");
        else               asm volatile("cp.async.wait_group 0;");
        __syncthreads();
        if (i + 2 < niter) {
            int k0 = (i+2) << 4;
            int nb = (i+2) % 3;
            uint32_t asb = as_sm + nb*(A_BUF*4);
            uint32_t wsb = ws_sm + nb*(W_BUF*4);
            #pragma unroll
            for (int t = 0; t < 2; t++) {
                int kk = a_kk0 + t*8;
                cpa16(asb + (kk*136 + a_ch0)*4, A + (size_t)(k0+kk)*lda + m0 + a_ch0);
                int nn = w_nn0 + t*64;
                uint32_t wd = wsb + (nn*28 + w_ck0)*4;
                if (n0 + nn < N) cpa16(wd, Wt + (size_t)(n0+nn)*K + k0 + w_ck0);
                else             cpa16z(wd, Wt);
            }
            asm volatile("cp.async.commit_group;");
        }
        int buf = i % 3;
        const float* Ab = Asm + buf*A_BUF;
        const float* Wb = Wsm + buf*W_BUF;
        int kbase = i << 4;
        #pragma unroll
        for (int ks = 0; ks < 2; ks++) {
            int k_lo = ks*8 + cq;
            float sc0 = 1.f, sh0 = 0.f, sc1 = 1.f, sh1 = 0.f;
            if (NORM) {
                sc0 = __ldg(&nsc[kbase + k_lo]);     sh0 = __ldg(&nsh[kbase + k_lo]);
                sc1 = __ldg(&nsc[kbase + k_lo + 4]); sh1 = __ldg(&nsh[kbase + k_lo + 4]);
            }
            unsigned af[4][4];
            #pragma unroll
            for (int mt = 0; mt < 4; mt++) {
                int mb = wm + mt*16 + r;
                float a0 = Ab[(k_lo    )*136 + mb];
                float a1 = Ab[(k_lo    )*136 + mb + 8];
                float a2 = Ab[(k_lo + 4)*136 + mb];
                float a3 = Ab[(k_lo + 4)*136 + mb + 8];
                if (NORM) {
                    a0 = a0*sc0 + sh0; a1 = a1*sc0 + sh0;
                    a2 = a2*sc1 + sh1; a3 = a3*sc1 + sh1;
                }
                af[mt][0] = __float_as_uint(a0); af[mt][1] = __float_as_uint(a1);
                af[mt][2] = __float_as_uint(a2); af[mt][3] = __float_as_uint(a3);
            }
            unsigned bf[4][2];
            #pragma unroll
            for (int nt = 0; nt < 4; nt++) {
                int nb2 = wn + nt*8 + r;
                bf[nt][0] = __float_as_uint(Wb[nb2*28 + k_lo]);
                bf[nt][1] = __float_as_uint(Wb[nb2*28 + k_lo + 4]);
            }
            #pragma unroll
            for (int mt = 0; mt < 4; mt++)
                #pragma unroll
                for (int nt = 0; nt < 4; nt++)
                    mma_tf32(cacc[mt][nt], af[mt], bf[nt]);
        }
        __syncthreads();
    }

    int er = lane >> 2, j2 = (lane & 3) * 2;
    if (FUSE == 0) {
        #pragma unroll
        for (int mt = 0; mt < 4; mt++)
            #pragma unroll
            for (int nt = 0; nt < 4; nt++) {
                int mb = m0 + wm + mt*16 + er;
                int nb = n0 + wn + nt*8 + j2;
                #pragma unroll
                for (int e = 0; e < 4; e++) {
                    int m = mb + ((e >> 1) ? 8 : 0);
                    int n = nb + (e & 1);
                    if (n < N) {
                        float v = cacc[mt][nt][e] + (bias ? bias[n] : 0.f);
                        if (ACT == 1) v = geluf(v);
                        size_t off = OUT_NM ? ((size_t)n*M + m) : ((size_t)m*N + n);
                        if (ACC) v += Co[off];
                        Co[off] = v;
                    }
                }
            }
    } else {
        // fused residual + LayerNorm epilogue (out_proj): tile rows are complete (N=96)
        float* tile = pool;                 // [128][97]
        float* mu_s = pool + 128*97;        // [128]
        float* rs_s = mu_s + 128;           // [128]
        float sk = skipp[0];
        #pragma unroll
        for (int mt = 0; mt < 4; mt++)
            #pragma unroll
            for (int nt = 0; nt < 4; nt++) {
                int mbl = wm + mt*16 + er;
                int nb = wn + nt*8 + j2;
                #pragma unroll
                for (int e = 0; e < 4; e++) {
                    int ml = mbl + ((e >> 1) ? 8 : 0);
                    int n = nb + (e & 1);
                    if (n < 96) {
                        float v = cacc[mt][nt][e] +
                                  sk * __ldg(&xflat[(size_t)(m0 + ml)*96 + n]);
                        tile[ml*97 + n] = v;
                    }
                }
            }
        __syncthreads();
        {
            int row = tid >> 1, half = tid & 1;
            const float* tp = tile + row*97 + half*48;
            float sum = 0.f, sq = 0.f;
            #pragma unroll 8
            for (int j = 0; j < 48; j++) { float v = tp[j]; sum += v; sq += v*v; }
            sum += __shfl_xor_sync(0xffffffffu, sum, 1);
            sq  += __shfl_xor_sync(0xffffffffu, sq,  1);
            if (half == 0) {
                float mu = sum / 96.f;
                float var = sq / 96.f - mu*mu;
                mu_s[row] = mu;
                rs_s[row] = rsqrtf(var + 1e-5f);
            }
        }
        __syncthreads();
        for (int idx = tid; idx < 96*128; idx += 256) {
            int row = idx & 127, c = idx >> 7;
            float v = tile[row*97 + c];
            float o = (v - mu_s[row]) * rs_s[row] * __ldg(&ln_g[c]) + __ldg(&ln_b[c]);
            Co[(size_t)c*M + m0 + row] = o;
        }
    }
}

// ---------------- LayerNorm1 over C with transpose ----------------
__global__ __launch_bounds__(256) void ln1_kernel(const float* __restrict__ x,
                                                  const float* __restrict__ g,
                                                  const float* __restrict__ bta) {
    __shared__ float s[96][33];
    __shared__ float mu_s[32], rs_s[32];
    int b = blockIdx.y;
    int l0 = blockIdx.x * 32;
    int tid = threadIdx.x;
    int tx = tid & 31, ty = tid >> 5;
    const float* xp = x + (size_t)b * C_ * L_;
    for (int c = ty; c < C_; c += 8)
        s[c][tx] = xp[(size_t)c * L_ + l0 + tx];
    __syncthreads();
    if (tid < 32) {
        float sum = 0.f, sq = 0.f;
        #pragma unroll 4
        for (int c = 0; c < C_; c++) { float v = s[c][tid]; sum += v; sq += v*v; }
        float mu = sum / 96.f;
        float var = sq / 96.f - mu*mu;
        mu_s[tid] = mu; rs_s[tid] = rsqrtf(var + 1e-5f);
    }
    __syncthreads();
    for (int idx = tid; idx < 96*32; idx += 256) {
        int c = idx % 96, l = idx / 96;
        g_xflat[(size_t)(b*L_ + l0 + l)*96 + c] = s[c][l];
    }
    for (int idx = tid; idx < 96*32; idx += 256) {
        int l = idx & 31, c = idx >> 5;
        float v = s[c][l];
        g_xnT[(size_t)c*NROWS + b*L_ + l0 + l] = (v - mu_s[l]) * rs_s[l] * g[c] + bta[c];
    }
}

// ---------------- causal depthwise conv1d (k=4) + SiLU ----------------
__global__ __launch_bounds__(256) void conv1d_kernel(const float* __restrict__ w,
                                                     const float* __restrict__ bias) {
    int idx = blockIdx.x * 256 + threadIdx.x;
    int lb = idx % (L_/4);
    int db = idx / (L_/4);
    if (db >= DINNER * B_) return;
    int b = db % B_, d = db / B_;
    const float* xp = g_xzT + (size_t)d*NROWS + (size_t)b*L_;
    float4 v = *(const float4*)(xp + lb*4);
    float4 p = make_float4(0.f, 0.f, 0.f, 0.f);
    if (lb > 0) p = *(const float4*)(xp + lb*4 - 4);
    float w0 = w[d*4+0], w1 = w[d*4+1], w2 = w[d*4+2], w3 = w[d*4+3];
    float bv = bias[d];
    float4 o;
    o.x = bv + p.y*w0 + p.z*w1 + p.w*w2 + v.x*w3;
    o.y = bv + p.z*w0 + p.w*w1 + v.x*w2 + v.y*w3;
    o.z = bv + p.w*w0 + v.x*w1 + v.y*w2 + v.z*w3;
    o.w = bv + v.x*w0 + v.y*w1 + v.z*w2 + v.w*w3;
    o.x = siluf(o.x); o.y = siluf(o.y); o.z = siluf(o.z); o.w = siluf(o.w);
    *(float4*)(g_uT + (size_t)d*NROWS + (size_t)b*L_ + lb*4) = o;
}

// ---------------- dt softplus, transposed out ----------------
__global__ __launch_bounds__(256) void dt2_kernel(const float* __restrict__ dtw,
                                                  const float* __restrict__ dtb) {
    __shared__ float ws[DINNER*6];
    __shared__ float bs[DINNER];
    int tid = threadIdx.x;
    int r0 = blockIdx.x * 256;
    for (int i = tid; i < DINNER*6; i += 256) ws[i] = dtw[i];
    if (tid < DINNER) bs[tid] = dtb[tid];
    __syncthreads();
    float x0 = g_xdT[0*NROWS + r0 + tid];
    float x1 = g_xdT[1*NROWS + r0 + tid];
    float x2 = g_xdT[2*NROWS + r0 + tid];
    float x3 = g_xdT[3*NROWS + r0 + tid];
    float x4 = g_xdT[4*NROWS + r0 + tid];
    float x5 = g_xdT[5*NROWS + r0 + tid];
    for (int d = 0; d < DINNER; d++) {
        float acc = bs[d];
        acc += x0*ws[d*6+0]; acc += x1*ws[d*6+1]; acc += x2*ws[d*6+2];
        acc += x3*ws[d*6+3]; acc += x4*ws[d*6+4]; acc += x5*ws[d*6+5];
        float sp = (acc > 20.f) ? acc : __logf(1.f + __expf(acc));
        g_dtT[(size_t)d*NROWS + r0 + tid] = sp;
    }
}

// ---------------- chunked selective scan ----------------
__global__ __launch_bounds__(128) void scan_phase1(const float* __restrict__ A_log) {
    int wid = (blockIdx.x * blockDim.x + threadIdx.x) >> 5;
    int lane = threadIdx.x & 31;
    int s = lane & 15, grp = lane >> 4;
    int pair = wid % 192;
    int chunk = wid / 192;
    int chan = pair*2 + grp;
    int b = chan / DINNER, d = chan % DINNER;
    float Aa = -expf(A_log[d*DSTATE + s]);
    float h = 0.f, P = 1.f;
    size_t base = (size_t)b*L_ + (size_t)chunk*CS;
    const float4* dtp = (const float4*)(g_dtT + (size_t)d*NROWS + base);
    const float4* up  = (const float4*)(g_uT  + (size_t)d*NROWS + base);
    const float4* bp  = (const float4*)(g_xdT + (size_t)(6+s)*NROWS + base);
    #pragma unroll 2
    for (int q = 0; q < CS/4; q++) {
        float4 dt4 = dtp[q], u4 = up[q], b4 = bp[q];
        float a;
        a = __expf(dt4.x*Aa); h = a*h + (dt4.x*u4.x)*b4.x; P *= a;
        a = __expf(dt4.y*Aa); h = a*h + (dt4.y*u4.y)*b4.y; P *= a;
        a = __expf(dt4.z*Aa); h = a*h + (dt4.z*u4.z)*b4.z; P *= a;
        a = __expf(dt4.w*Aa); h = a*h + (dt4.w*u4.w)*b4.w; P *= a;
    }
    int o = (chunk*384 + chan)*DSTATE + s;
    g_F[o] = h; g_P[o] = P;
}

__global__ __launch_bounds__(256) void scan_phase2() {
    int t = blockIdx.x * 256 + threadIdx.x;
    if (t >= 384*DSTATE) return;
    float H = 0.f;
    for (int j = 0; j < NC; j++) {
        int o = j*384*DSTATE + t;
        g_Hi[o] = H;
        H = g_F[o] + g_P[o]*H;
    }
}

__global__ __launch_bounds__(128) void scan_phase3(const float* __restrict__ A_log,
                                                   const float* __restrict__ Dp) {
    int wid = (blockIdx.x * blockDim.x + threadIdx.x) >> 5;
    int lane = threadIdx.x & 31;
    int s = lane & 15, grp = lane >> 4;
    int pair = wid % 192;
    int chunk = wid / 192;
    int chan = pair*2 + grp;
    int b = chan / DINNER, d = chan % DINNER;
    float Aa = -expf(A_log[d*DSTATE + s]);
    float Dpd = Dp[d];
    float h = g_Hi[(chunk*384 + chan)*DSTATE + s];
    size_t base = (size_t)b*L_ + (size_t)chunk*CS;
    const float4* dtp = (const float4*)(g_dtT + (size_t)d*NROWS + base);
    const float4* up  = (const float4*)(g_uT  + (size_t)d*NROWS + base);
    const float4* bp  = (const float4*)(g_xdT + (size_t)(6+s)*NROWS + base);
    const float4* cp  = (const float4*)(g_xdT + (size_t)(22+s)*NROWS + base);
    const float4* zp  = (const float4*)(g_xzT + (size_t)(192+d)*NROWS + base);
    float4* yp = (float4*)(g_yT + (size_t)d*NROWS + base);
    for (int q = 0; q < CS/4; q++) {
        float4 dt4 = dtp[q], u4 = up[q], b4 = bp[q], c4 = cp[q], z4 = zp[q];
        float4 yv;
        float a, p;
        a = __expf(dt4.x*Aa); h = a*h + (dt4.x*u4.x)*b4.x;
        p = h * c4.x;
        p += __shfl_xor_sync(0xffffffffu, p, 8);
        p += __shfl_xor_sync(0xffffffffu, p, 4);
        p += __shfl_xor_sync(0xffffffffu, p, 2);
        p += __shfl_xor_sync(0xffffffffu, p, 1);
        yv.x = (p + u4.x*Dpd) * siluf(z4.x);
        a = __expf(dt4.y*Aa); h = a*h + (dt4.y*u4.y)*b4.y;
        p = h * c4.y;
        p += __shfl_xor_sync(0xffffffffu, p, 8);
        p += __shfl_xor_sync(0xffffffffu, p, 4);
        p += __shfl_xor_sync(0xffffffffu, p, 2);
        p += __shfl_xor_sync(0xffffffffu, p, 1);
        yv.y = (p + u4.y*Dpd) * siluf(z4.y);
        a = __expf(dt4.z*Aa); h = a*h + (dt4.z*u4.z)*b4.z;
        p = h * c4.z;
        p += __shfl_xor_sync(0xffffffffu, p, 8);
        p += __shfl_xor_sync(0xffffffffu, p, 4);
        p += __shfl_xor_sync(0xffffffffu, p, 2);
        p += __shfl_xor_sync(0xffffffffu, p, 1);
        yv.z = (p + u4.z*Dpd) * siluf(z4.z);
        a = __expf(dt4.w*Aa); h = a*h + (dt4.w*u4.w)*b4.w;
        p = h * c4.w;
        p += __shfl_xor_sync(0xffffffffu, p, 8);
        p += __shfl_xor_sync(0xffffffffu, p, 4);
        p += __shfl_xor_sync(0xffffffffu, p, 2);
        p += __shfl_xor_sync(0xffffffffu, p, 1);
        yv.w = (p + u4.w*Dpd) * siluf(z4.w);
        if (s == 0) yp[q] = yv;
    }
}

// ---------------- launch ----------------
extern "C" void kernel_launch(void* const* d_in, const int* in_sizes, int n_in,
                              void* d_out, int out_size) {
    const float* x     = (const float*)d_in[0];
    const float* dw_w  = (const float*)d_in[1];
    const float* dw_b  = (const float*)d_in[2];
    const float* gn_g  = (const float*)d_in[3];
    const float* gn_b  = (const float*)d_in[4];
    const float* pw1_w = (const float*)d_in[5];
    const float* pw1_b = (const float*)d_in[6];
    const float* pw2_w = (const float*)d_in[7];
    const float* pw2_b = (const float*)d_in[8];
    const float* ln_g  = (const float*)d_in[9];
    const float* ln_b  = (const float*)d_in[10];
    const float* skip  = (const float*)d_in[11];
    const float* inpw  = (const float*)d_in[12];
    const float* c1w   = (const float*)d_in[13];
    const float* c1b   = (const float*)d_in[14];
    const float* xpw   = (const float*)d_in[15];
    const float* dtw   = (const float*)d_in[16];
    const float* dtb   = (const float*)d_in[17];
    const float* A_log = (const float*)d_in[18];
    const float* Dp    = (const float*)d_in[19];
    const float* outpw = (const float*)d_in[20];
    const float* projw = (const float*)d_in[21];
    const float* projb = (const float*)d_in[22];
    float* out = (float*)d_out;

    float *p_h1, *p_h2, *p_xflat, *p_xnT, *p_xzT, *p_uT, *p_xdT, *p_yT, *p_xm2T, *p_sc, *p_sh;
    cudaGetSymbolAddress((void**)&p_h1,    g_h1);
    cudaGetSymbolAddress((void**)&p_h2,    g_h2);
    cudaGetSymbolAddress((void**)&p_xflat, g_xflat);
    cudaGetSymbolAddress((void**)&p_xnT,   g_xnT);
    cudaGetSymbolAddress((void**)&p_xzT,   g_xzT);
    cudaGetSymbolAddress((void**)&p_uT,    g_uT);
    cudaGetSymbolAddress((void**)&p_xdT,   g_xdT);
    cudaGetSymbolAddress((void**)&p_yT,    g_yT);
    cudaGetSymbolAddress((void**)&p_xm2T,  g_xm2T);
    cudaGetSymbolAddress((void**)&p_sc,    g_gnsc);
    cudaGetSymbolAddress((void**)&p_sh,    g_gnsh);

    // raise dynamic smem cap for all gemm instantiations (idempotent)
    cudaFuncSetAttribute((const void*)gemmt_kernel<true,1,false,true,0>,
                         cudaFuncAttributeMaxDynamicSharedMemorySize, POOL_BYTES);
    cudaFuncSetAttribute((const void*)gemmt_kernel<true,0,false,false,0>,
                         cudaFuncAttributeMaxDynamicSharedMemorySize, POOL_BYTES);
    cudaFuncSetAttribute((const void*)gemmt_kernel<false,0,false,false,1>,
                         cudaFuncAttributeMaxDynamicSharedMemorySize, POOL_BYTES);
    cudaFuncSetAttribute((const void*)gemmt_kernel<true,0,true,false,0>,
                         cudaFuncAttributeMaxDynamicSharedMemorySize, POOL_BYTES);

    // ---- conv branch ----
    zero_stats_kernel<<<1,32>>>();
    dwconv3d_kernel<<<dim3(3,3,B_*C_), dim3(16,16)>>>(x, dw_w, dw_b);
    gn_scale_kernel<<<1,256>>>(gn_g, gn_b);
    gemmt_kernel<true,1,false,true,0><<<dim3(L_/128, 3, B_),256,POOL_BYTES>>>(
        p_h1, L_, (size_t)C_*L_, pw1_w, pw1_b, p_h2, L_, 4*C_, C_, (size_t)4*C_*L_,
        p_sc, p_sh, nullptr, nullptr, nullptr, nullptr);
    gemmt_kernel<true,0,false,false,0><<<dim3(L_/128, 1, B_),256,POOL_BYTES>>>(
        p_h2, L_, (size_t)4*C_*L_, pw2_w, pw2_b, out, L_, C_, 4*C_, (size_t)C_*L_,
        nullptr, nullptr, nullptr, nullptr, nullptr, nullptr);

    // ---- mamba branch ----
    ln1_kernel<<<dim3(L_/32, B_),256>>>(x, ln_g, ln_b);
    gemmt_kernel<true,0,false,false,0><<<dim3(NROWS/128, 3, 1),256,POOL_BYTES>>>(
        p_xnT, NROWS, 0, inpw, nullptr, p_xzT, NROWS, 2*DINNER, C_, 0,
        nullptr, nullptr, nullptr, nullptr, nullptr, nullptr);
    conv1d_kernel<<<(DINNER*B_*(L_/4))/256,256>>>(c1w, c1b);
    gemmt_kernel<true,0,false,false,0><<<dim3(NROWS/128, 1, 1),256,POOL_BYTES>>>(
        p_uT, NROWS, 0, xpw, nullptr, p_xdT, NROWS, 38, DINNER, 0,
        nullptr, nullptr, nullptr, nullptr, nullptr, nullptr);
    dt2_kernel<<<NROWS/256,256>>>(dtw, dtb);
    scan_phase1<<<(192*NC)/4, 128>>>(A_log);
    scan_phase2<<<24,256>>>();
    scan_phase3<<<(192*NC)/4, 128>>>(A_log, Dp);
    // out_proj + residual + LN2 fused -> xm2T
    gemmt_kernel<false,0,false,false,1><<<dim3(NROWS/128, 1, 1),256,POOL_BYTES>>>(
        p_yT, NROWS, 0, outpw, nullptr, p_xm2T, NROWS, C_, DINNER, 0,
        nullptr, nullptr, ln_g, ln_b, skip, p_xflat);
    // proj: accumulate onto conv_out in d_out
    gemmt_kernel<true,0,true,false,0><<<dim3(L_/128, 1, B_),256,POOL_BYTES>>>(
        p_xm2T, NROWS, (size_t)L_, projw, projb, out, L_, C_, C_, (size_t)C_*L_,
        nullptr, nullptr, nullptr, nullptr, nullptr, nullptr);
}